// round 5
// baseline (speedup 1.0000x reference)
#include <cuda_runtime.h>
#include <cuda_bf16.h>
#include <stdint.h>

#define BATCH 4
#define SEQ   2048
#define DIM   768
#define MROWS 8192            // B*S
#define NQKV  2304            // 3*DIM

// ---------------- device scratch: split-bf16 planes -------------------------
__device__ __align__(128) __nv_bfloat16 g_xh[(long)MROWS * DIM];
__device__ __align__(128) __nv_bfloat16 g_xl[(long)MROWS * DIM];
__device__ __align__(128) __nv_bfloat16 g_wh[(long)NQKV * DIM];
__device__ __align__(128) __nv_bfloat16 g_wl[(long)NQKV * DIM];
__device__ __align__(128) __nv_bfloat16 g_qh[(long)MROWS * DIM];
__device__ __align__(128) __nv_bfloat16 g_ql[(long)MROWS * DIM];
__device__ __align__(128) __nv_bfloat16 g_kh[(long)MROWS * DIM];
__device__ __align__(128) __nv_bfloat16 g_kl[(long)MROWS * DIM];
__device__ __align__(128) __nv_bfloat16 g_vh[(long)MROWS * DIM];   // [b*S+s][d]
__device__ __align__(128) __nv_bfloat16 g_vl[(long)MROWS * DIM];
__device__ __align__(128) __nv_bfloat16 g_ph[(size_t)BATCH * SEQ * SEQ];
__device__ __align__(128) __nv_bfloat16 g_pl[(size_t)BATCH * SEQ * SEQ];
__device__ float g_S[(size_t)BATCH * SEQ * SEQ];

// ---------------- PTX helpers (portable, no arch-'a' features) --------------
__device__ __forceinline__ uint32_t smem_u32(const void* p) {
    uint32_t a;
    asm("{ .reg .u64 t; cvta.to.shared.u64 t, %1; cvt.u32.u64 %0, t; }"
        : "=r"(a) : "l"(p));
    return a;
}
__device__ __forceinline__ void ldsm4(uint32_t r[4], uint32_t addr) {
    asm volatile("ldmatrix.sync.aligned.m8n8.x4.shared.b16 {%0,%1,%2,%3}, [%4];"
                 : "=r"(r[0]), "=r"(r[1]), "=r"(r[2]), "=r"(r[3]) : "r"(addr));
}
__device__ __forceinline__ void ldsm4t(uint32_t r[4], uint32_t addr) {
    asm volatile("ldmatrix.sync.aligned.m8n8.x4.trans.shared.b16 {%0,%1,%2,%3}, [%4];"
                 : "=r"(r[0]), "=r"(r[1]), "=r"(r[2]), "=r"(r[3]) : "r"(addr));
}
__device__ __forceinline__ void mma16816(float d[4], const uint32_t a[4],
                                         const uint32_t b[2]) {
    asm volatile(
        "mma.sync.aligned.m16n8k16.row.col.f32.bf16.bf16.f32 "
        "{%0,%1,%2,%3}, {%4,%5,%6,%7}, {%8,%9}, {%0,%1,%2,%3};"
        : "+f"(d[0]), "+f"(d[1]), "+f"(d[2]), "+f"(d[3])
        : "r"(a[0]), "r"(a[1]), "r"(a[2]), "r"(a[3]), "r"(b[0]), "r"(b[1]));
}
__device__ __forceinline__ void cpa16(uint32_t dst, const void* src) {
    asm volatile("cp.async.cg.shared.global [%0], [%1], 16;" :: "r"(dst), "l"(src));
}
__device__ __forceinline__ void cp_commit() {
    asm volatile("cp.async.commit_group;" ::: "memory");
}
template <int N> __device__ __forceinline__ void cp_wait() {
    asm volatile("cp.async.wait_group %0;" :: "n"(N) : "memory");
}
__device__ __forceinline__ void split_bf16(float v, __nv_bfloat16& h, __nv_bfloat16& l) {
    h = __float2bfloat16(v);
    l = __float2bfloat16(v - __bfloat162float(h));
}

// ---------------- smem geometry ----------------------------------------------
// A/B/P tiles: 128 rows x 16 k, padded pitch 24 bf16 (48B) -> conflict-free.
#define ROWB    48
#define PLANE   6144                       // 128*48
#define NT_MAT  (2 * PLANE)                // one matrix (hi+lo)
#define NT_STG  (2 * NT_MAT)               // A+B per stage = 24576
#define NT_SMEM (3 * NT_STG)               // 73728

// V tile: 16 rows x 128 cols, pitch 136 bf16 (272B)
#define VROWB   272
#define VPLANE  (16 * VROWB)               // 4352
#define PV_STG  (NT_MAT + 2 * VPLANE)      // 12288 + 8704 = 20992
#define PV_SMEM (3 * PV_STG)               // 62976

// ---------------- stage compute: warp tile 64x64 ------------------------------
// NT: B stored [n][k] rows. acc[4][8][4]
__device__ __forceinline__ void stage_nt(uint32_t sa, uint32_t sb, int lane,
                                         int wm, int wn, float acc[4][8][4]) {
    const int lr = lane & 15;
    const uint32_t lc16 = (lane >> 4) << 4;
    uint32_t bh[8][2], bl[8][2];
#pragma unroll
    for (int j = 0; j < 4; ++j) {
        uint32_t t4[4];
        const uint32_t roff = (uint32_t)(wn * 64 + j * 16 + lr) * ROWB + lc16;
        ldsm4(t4, sb + roff);
        bh[j*2][0] = t4[0]; bh[j*2+1][0] = t4[1];
        bh[j*2][1] = t4[2]; bh[j*2+1][1] = t4[3];
        ldsm4(t4, sb + PLANE + roff);
        bl[j*2][0] = t4[0]; bl[j*2+1][0] = t4[1];
        bl[j*2][1] = t4[2]; bl[j*2+1][1] = t4[3];
    }
#pragma unroll
    for (int mi = 0; mi < 4; ++mi) {
        uint32_t ah[4], al[4];
        const uint32_t roff = (uint32_t)(wm * 64 + mi * 16 + lr) * ROWB + lc16;
        ldsm4(ah, sa + roff);
        ldsm4(al, sa + PLANE + roff);
#pragma unroll
        for (int nj = 0; nj < 8; ++nj) {
            mma16816(acc[mi][nj], ah, bh[nj]);
            mma16816(acc[mi][nj], ah, bl[nj]);
            mma16816(acc[mi][nj], al, bh[nj]);
        }
    }
}

// PV: V stored [k(16)][n(128)], trans ldmatrix.
__device__ __forceinline__ void stage_pv(uint32_t sa, uint32_t sv, int lane,
                                         int wm, int wn, float acc[4][8][4]) {
    const int lr = lane & 15;
    const uint32_t lc16 = (lane >> 4) << 4;
    uint32_t bh[8][2], bl[8][2];
#pragma unroll
    for (int j = 0; j < 4; ++j) {
        uint32_t t4[4];
        const uint32_t off = (uint32_t)lr * VROWB + (uint32_t)(wn * 64 + j * 16) * 2 + lc16;
        ldsm4t(t4, sv + off);
        bh[j*2][0] = t4[0]; bh[j*2][1] = t4[1];
        bh[j*2+1][0] = t4[2]; bh[j*2+1][1] = t4[3];
        ldsm4t(t4, sv + VPLANE + off);
        bl[j*2][0] = t4[0]; bl[j*2][1] = t4[1];
        bl[j*2+1][0] = t4[2]; bl[j*2+1][1] = t4[3];
    }
#pragma unroll
    for (int mi = 0; mi < 4; ++mi) {
        uint32_t ah[4], al[4];
        const uint32_t roff = (uint32_t)(wm * 64 + mi * 16 + lr) * ROWB + lc16;
        ldsm4(ah, sa + roff);
        ldsm4(al, sa + PLANE + roff);
#pragma unroll
        for (int nj = 0; nj < 8; ++nj) {
            mma16816(acc[mi][nj], ah, bh[nj]);
            mma16816(acc[mi][nj], ah, bl[nj]);
            mma16816(acc[mi][nj], al, bh[nj]);
        }
    }
}

#define ACC_INIT float acc[4][8][4];                                    \
    _Pragma("unroll") for (int _i = 0; _i < 4; ++_i)                    \
    _Pragma("unroll") for (int _j = 0; _j < 8; ++_j)                    \
    _Pragma("unroll") for (int _k = 0; _k < 4; ++_k) acc[_i][_j][_k] = 0.f;

// ---------------- cp.async stage issue ----------------------------------------
// NT: 8 x 16B per thread (A row=tid: 2 chunks x 2 planes; B same).
__device__ __forceinline__ void issue_nt(uint32_t su, int tid,
                                         const __nv_bfloat16* Ah, const __nv_bfloat16* Al,
                                         const __nv_bfloat16* Bh, const __nv_bfloat16* Bl,
                                         long lda, long ldb, int k0) {
    const uint32_t so = (uint32_t)tid * ROWB;
    const long ga = (long)tid * lda + k0;
    const long gb = (long)tid * ldb + k0;
#pragma unroll
    for (int ch = 0; ch < 2; ++ch) {
        cpa16(su + so + ch * 16,                     Ah + ga + ch * 8);
        cpa16(su + PLANE + so + ch * 16,             Al + ga + ch * 8);
        cpa16(su + NT_MAT + so + ch * 16,            Bh + gb + ch * 8);
        cpa16(su + NT_MAT + PLANE + so + ch * 16,    Bl + gb + ch * 8);
    }
}
// PV: P row=tid (4 chunks), V row=tid>>3, 2 chunks x 2 planes.
__device__ __forceinline__ void issue_pv(uint32_t su, int tid,
                                         const __nv_bfloat16* Ph, const __nv_bfloat16* Pl,
                                         const __nv_bfloat16* Vh, const __nv_bfloat16* Vl,
                                         int n0, int k0) {
    const uint32_t so = (uint32_t)tid * ROWB;
    const long gp = (long)tid * SEQ + k0;
#pragma unroll
    for (int ch = 0; ch < 2; ++ch) {
        cpa16(su + so + ch * 16,         Ph + gp + ch * 8);
        cpa16(su + PLANE + so + ch * 16, Pl + gp + ch * 8);
    }
    const int vr = tid >> 3;
    const int vc = (tid & 7) * 2;                     // chunk pair
    const uint32_t vo = su + NT_MAT + (uint32_t)vr * VROWB + (uint32_t)vc * 16;
    const long gv = (long)(k0 + vr) * DIM + n0 + vc * 8;
#pragma unroll
    for (int ch = 0; ch < 2; ++ch) {
        cpa16(vo + ch * 16,          Vh + gv + ch * 8);
        cpa16(vo + VPLANE + ch * 16, Vl + gv + ch * 8);
    }
}

// ---------------- kernel 0: fp32 -> split planes -----------------------------
__global__ __launch_bounds__(256) void cvt_kernel(const float* __restrict__ src,
                                                  int which, long row0) {
    const long i = ((long)blockIdx.x * 256 + threadIdx.x) * 4;
    __nv_bfloat16* dh = (which == 0) ? g_xh : g_wh;
    __nv_bfloat16* dl = (which == 0) ? g_xl : g_wl;
    dh += row0 * DIM;
    dl += row0 * DIM;
    const float4 v = *(const float4*)(src + i);
    float a[4] = { v.x, v.y, v.z, v.w };
    __nv_bfloat16 h[4], l[4];
#pragma unroll
    for (int j = 0; j < 4; ++j) split_bf16(a[j], h[j], l[j]);
    *(uint2*)(dh + i) = *(uint2*)h;
    *(uint2*)(dl + i) = *(uint2*)l;
}

// ---------------- shared NT mainloop ------------------------------------------
#define NT_BODY(Ah, Al, Bh, Bl, lda, ldb, NC)                                  \
    extern __shared__ __align__(128) char dsm[];                               \
    const int tid = threadIdx.x;                                               \
    const int lane = tid & 31, wid = tid >> 5;                                 \
    const int wm = wid & 1, wn = wid >> 1;                                     \
    const uint32_t su = smem_u32(dsm);                                         \
    ACC_INIT;                                                                  \
    issue_nt(su,              tid, Ah, Al, Bh, Bl, lda, ldb, 0);  cp_commit(); \
    issue_nt(su + NT_STG,     tid, Ah, Al, Bh, Bl, lda, ldb, 16); cp_commit(); \
    for (int c = 0; c < (NC); ++c) {                                           \
        if (c + 1 < (NC)) cp_wait<1>(); else cp_wait<0>();                     \
        __syncthreads();                                                       \
        if (c + 2 < (NC)) {                                                    \
            issue_nt(su + ((c + 2) % 3) * NT_STG, tid, Ah, Al, Bh, Bl,         \
                     lda, ldb, (c + 2) * 16);                                  \
        }                                                                      \
        cp_commit();                                                           \
        const uint32_t sb0 = su + (c % 3) * NT_STG;                            \
        stage_nt(sb0, sb0 + NT_MAT, lane, wm, wn, acc);                        \
        __syncthreads();                                                       \
    }

// ---------------- kernel 1: QKV projection (NT) -------------------------------
__global__ __launch_bounds__(128) void gemm_qkv() {
    const int m0 = blockIdx.x * 128;
    const int n0 = blockIdx.y * 128;
    NT_BODY(g_xh + (long)m0 * DIM, g_xl + (long)m0 * DIM,
            g_wh + (long)n0 * DIM, g_wl + (long)n0 * DIM,
            DIM, DIM, DIM / 16);

    const int mat = n0 / DIM;
    const int nl0 = n0 % DIM;
    __nv_bfloat16* dh = (mat == 0) ? g_qh : ((mat == 1) ? g_kh : g_vh);
    __nv_bfloat16* dl = (mat == 0) ? g_ql : ((mat == 1) ? g_kl : g_vl);
    const int r = lane >> 2, cc = (lane & 3) * 2;
#pragma unroll
    for (int mi = 0; mi < 4; ++mi)
#pragma unroll
        for (int nj = 0; nj < 8; ++nj)
#pragma unroll
            for (int h2 = 0; h2 < 2; ++h2) {
                const int m = m0 + wm * 64 + mi * 16 + r + h2 * 8;
                const int n = nl0 + wn * 64 + nj * 8 + cc;
                __nv_bfloat162 hv, lv;
                split_bf16(acc[mi][nj][h2 * 2 + 0], hv.x, lv.x);
                split_bf16(acc[mi][nj][h2 * 2 + 1], hv.y, lv.y);
                *(__nv_bfloat162*)(dh + (long)m * DIM + n) = hv;
                *(__nv_bfloat162*)(dl + (long)m * DIM + n) = lv;
            }
}

// ---------------- kernel 2: causal scores (NT) --------------------------------
__global__ __launch_bounds__(128) void gemm_scores() {
    const int mi_t = gridDim.x - 1 - blockIdx.x;    // longest first
    if ((int)blockIdx.y > mi_t) return;             // fully above diagonal
    const int m0 = mi_t * 128, n0 = blockIdx.y * 128, b = blockIdx.z;
    NT_BODY(g_qh + ((long)b * SEQ + m0) * DIM, g_ql + ((long)b * SEQ + m0) * DIM,
            g_kh + ((long)b * SEQ + n0) * DIM, g_kl + ((long)b * SEQ + n0) * DIM,
            DIM, DIM, DIM / 16);

    const float scale = 0.036084391824351615f;      // 1/sqrt(768)
    float* Sg = g_S + (size_t)b * SEQ * SEQ;
    const int r = lane >> 2, cc = (lane & 3) * 2;
#pragma unroll
    for (int mi = 0; mi < 4; ++mi)
#pragma unroll
        for (int nj = 0; nj < 8; ++nj)
#pragma unroll
            for (int h2 = 0; h2 < 2; ++h2) {
                const int m = m0 + wm * 64 + mi * 16 + r + h2 * 8;
                const int n = n0 + wn * 64 + nj * 8 + cc;
                float2 v = make_float2(acc[mi][nj][h2 * 2 + 0] * scale,
                                       acc[mi][nj][h2 * 2 + 1] * scale);
                *(float2*)(Sg + (size_t)m * SEQ + n) = v;
            }
}

// ---------------- kernel 3: softmax + split-bf16 P -----------------------------
__global__ __launch_bounds__(256) void softmax_kernel() {
    const int rid = blockIdx.x;
    const int q = rid & (SEQ - 1);
    float* __restrict__ row = g_S + (size_t)rid * SEQ;
    __nv_bfloat16* __restrict__ ph = g_ph + (size_t)rid * SEQ;
    __nv_bfloat16* __restrict__ pl = g_pl + (size_t)rid * SEQ;
    const int L = q + 1;
    const int tid = threadIdx.x;
    __shared__ float red[256];

    float m = -1e30f;
    for (int k = tid; k < L; k += 256) m = fmaxf(m, row[k]);
    red[tid] = m;
    __syncthreads();
#pragma unroll
    for (int s = 128; s > 0; s >>= 1) {
        if (tid < s) red[tid] = fmaxf(red[tid], red[tid + s]);
        __syncthreads();
    }
    m = red[0];
    __syncthreads();

    float ssum = 0.f;
    for (int k = tid; k < L; k += 256) {
        float e = __expf(row[k] - m);
        row[k] = e;
        ssum += e;
    }
    red[tid] = ssum;
    __syncthreads();
#pragma unroll
    for (int s = 128; s > 0; s >>= 1) {
        if (tid < s) red[tid] += red[tid + s];
        __syncthreads();
    }
    const float inv = 1.0f / red[0];

    for (int k = tid; k < L; k += 256) {
        __nv_bfloat16 h, l;
        split_bf16(row[k] * inv, h, l);
        ph[k] = h;
        pl[k] = l;
    }
    const int kend = (q & ~127) + 128;
    const __nv_bfloat16 z = __float2bfloat16(0.f);
    for (int k = L + tid; k < kend; k += 256) { ph[k] = z; pl[k] = z; }
}

// ---------------- kernel 4: O = P V --------------------------------------------
__global__ __launch_bounds__(128) void gemm_pv(float* __restrict__ out) {
    const int mi_t = gridDim.x - 1 - blockIdx.x;    // longest K first
    const int m0 = mi_t * 128, n0 = blockIdx.y * 128, b = blockIdx.z;
    const __nv_bfloat16* Ph = g_ph + ((size_t)b * SEQ + m0) * SEQ;
    const __nv_bfloat16* Pl = g_pl + ((size_t)b * SEQ + m0) * SEQ;
    const __nv_bfloat16* Vh = g_vh + (long)b * SEQ * DIM;
    const __nv_bfloat16* Vl = g_vl + (long)b * SEQ * DIM;

    extern __shared__ __align__(128) char dsm[];
    const int tid = threadIdx.x;
    const int lane = tid & 31, wid = tid >> 5;
    const int wm = wid & 1, wn = wid >> 1;
    const uint32_t su = smem_u32(dsm);
    ACC_INIT;
    const int NC = (m0 + 128) / 16;

    issue_pv(su,          tid, Ph, Pl, Vh, Vl, n0, 0);  cp_commit();
    issue_pv(su + PV_STG, tid, Ph, Pl, Vh, Vl, n0, 16); cp_commit();
    for (int c = 0; c < NC; ++c) {
        if (c + 1 < NC) cp_wait<1>(); else cp_wait<0>();
        __syncthreads();
        if (c + 2 < NC) {
            issue_pv(su + ((c + 2) % 3) * PV_STG, tid, Ph, Pl, Vh, Vl, n0,
                     (c + 2) * 16);
        }
        cp_commit();
        const uint32_t sb0 = su + (c % 3) * PV_STG;
        stage_pv(sb0, sb0 + NT_MAT, lane, wm, wn, acc);
        __syncthreads();
    }

    float* Og = out + (long)b * SEQ * DIM;
    const int r = lane >> 2, cc = (lane & 3) * 2;
#pragma unroll
    for (int mi = 0; mi < 4; ++mi)
#pragma unroll
        for (int nj = 0; nj < 8; ++nj)
#pragma unroll
            for (int h2 = 0; h2 < 2; ++h2) {
                const int m = m0 + wm * 64 + mi * 16 + r + h2 * 8;
                const int n = n0 + wn * 64 + nj * 8 + cc;
                float2 v = make_float2(acc[mi][nj][h2 * 2 + 0],
                                       acc[mi][nj][h2 * 2 + 1]);
                *(float2*)(Og + (long)m * DIM + n) = v;
            }
}

// ---------------- launch ---------------------------------------------------------
extern "C" void kernel_launch(void* const* d_in, const int* in_sizes, int n_in,
                              void* d_out, int out_size) {
    const float* x  = (const float*)d_in[0];
    const float* Wq = (const float*)d_in[1];
    const float* Wk = (const float*)d_in[2];
    const float* Wv = (const float*)d_in[3];
    float* out = (float*)d_out;

    cudaFuncSetAttribute(gemm_qkv,    cudaFuncAttributeMaxDynamicSharedMemorySize, NT_SMEM);
    cudaFuncSetAttribute(gemm_scores, cudaFuncAttributeMaxDynamicSharedMemorySize, NT_SMEM);
    cudaFuncSetAttribute(gemm_pv,     cudaFuncAttributeMaxDynamicSharedMemorySize, PV_SMEM);

    cvt_kernel<<<(long)MROWS * DIM / 4 / 256, 256>>>(x,  0, 0);
    cvt_kernel<<<(long)DIM * DIM / 4 / 256, 256>>>(Wq, 1, 0);
    cvt_kernel<<<(long)DIM * DIM / 4 / 256, 256>>>(Wk, 1, DIM);
    cvt_kernel<<<(long)DIM * DIM / 4 / 256, 256>>>(Wv, 1, 2 * DIM);

    gemm_qkv<<<dim3(MROWS / 128, NQKV / 128), 128, NT_SMEM>>>();
    gemm_scores<<<dim3(SEQ / 128, SEQ / 128, BATCH), 128, NT_SMEM>>>();
    softmax_kernel<<<BATCH * SEQ, 256>>>();
    gemm_pv<<<dim3(SEQ / 128, DIM / 128, BATCH), 128, PV_SMEM>>>(out);
}

// round 6
// speedup vs baseline: 1.1691x; 1.1691x over previous
#include <cuda_runtime.h>
#include <cuda_bf16.h>
#include <stdint.h>

#define BATCH 4
#define SEQ   2048
#define DIM   768
#define MROWS 8192            // B*S
#define NQKV  2304            // 3*DIM

// ---------------- device scratch: split-bf16 planes -------------------------
__device__ __align__(128) __nv_bfloat16 g_xh[(long)MROWS * DIM];
__device__ __align__(128) __nv_bfloat16 g_xl[(long)MROWS * DIM];
__device__ __align__(128) __nv_bfloat16 g_wh[(long)NQKV * DIM];
__device__ __align__(128) __nv_bfloat16 g_wl[(long)NQKV * DIM];
__device__ __align__(128) __nv_bfloat16 g_qh[(long)MROWS * DIM];
__device__ __align__(128) __nv_bfloat16 g_ql[(long)MROWS * DIM];
__device__ __align__(128) __nv_bfloat16 g_kh[(long)MROWS * DIM];
__device__ __align__(128) __nv_bfloat16 g_kl[(long)MROWS * DIM];
__device__ __align__(128) __nv_bfloat16 g_vh[(long)MROWS * DIM];   // [b*S+s][d]
__device__ __align__(128) __nv_bfloat16 g_vl[(long)MROWS * DIM];
__device__ __align__(128) __nv_bfloat16 g_ph[(size_t)BATCH * SEQ * SEQ];
__device__ __align__(128) __nv_bfloat16 g_pl[(size_t)BATCH * SEQ * SEQ];
__device__ float g_S[(size_t)BATCH * SEQ * SEQ];

// ---------------- PTX helpers (portable, no arch-'a' features) --------------
__device__ __forceinline__ uint32_t smem_u32(const void* p) {
    uint32_t a;
    asm("{ .reg .u64 t; cvta.to.shared.u64 t, %1; cvt.u32.u64 %0, t; }"
        : "=r"(a) : "l"(p));
    return a;
}
__device__ __forceinline__ void ldsm4(uint32_t r[4], uint32_t addr) {
    asm volatile("ldmatrix.sync.aligned.m8n8.x4.shared.b16 {%0,%1,%2,%3}, [%4];"
                 : "=r"(r[0]), "=r"(r[1]), "=r"(r[2]), "=r"(r[3]) : "r"(addr));
}
__device__ __forceinline__ void ldsm4t(uint32_t r[4], uint32_t addr) {
    asm volatile("ldmatrix.sync.aligned.m8n8.x4.trans.shared.b16 {%0,%1,%2,%3}, [%4];"
                 : "=r"(r[0]), "=r"(r[1]), "=r"(r[2]), "=r"(r[3]) : "r"(addr));
}
__device__ __forceinline__ void mma16816(float d[4], const uint32_t a[4],
                                         const uint32_t b[2]) {
    asm volatile(
        "mma.sync.aligned.m16n8k16.row.col.f32.bf16.bf16.f32 "
        "{%0,%1,%2,%3}, {%4,%5,%6,%7}, {%8,%9}, {%0,%1,%2,%3};"
        : "+f"(d[0]), "+f"(d[1]), "+f"(d[2]), "+f"(d[3])
        : "r"(a[0]), "r"(a[1]), "r"(a[2]), "r"(a[3]), "r"(b[0]), "r"(b[1]));
}
__device__ __forceinline__ void cpa16(uint32_t dst, const void* src) {
    asm volatile("cp.async.cg.shared.global [%0], [%1], 16;" :: "r"(dst), "l"(src));
}
__device__ __forceinline__ void cp_commit() {
    asm volatile("cp.async.commit_group;" ::: "memory");
}
template <int N> __device__ __forceinline__ void cp_wait() {
    asm volatile("cp.async.wait_group %0;" :: "n"(N) : "memory");
}
__device__ __forceinline__ void split_bf16(float v, __nv_bfloat16& h, __nv_bfloat16& l) {
    h = __float2bfloat16(v);
    l = __float2bfloat16(v - __bfloat162float(h));
}

// ---------------- smem geometry ----------------------------------------------
// A/B/P tiles: 128 rows x 16 k, padded pitch 24 bf16 (48B) -> conflict-free.
#define ROWB    48
#define PLANE   6144                       // 128*48
#define MAT2    (2 * PLANE)                // hi+lo planes of one matrix = 12288
#define NT_STG  (2 * MAT2)                 // A+B per stage = 24576
#define NT_SMEM (3 * NT_STG)               // 73728

// V tile: 16 rows x 128 cols, pitch 136 bf16 (272B)
#define VROWB   272
#define VPLANE  (16 * VROWB)               // 4352
#define PV_STG  (MAT2 + 2 * VPLANE)        // 12288 + 8704 = 20992
#define PV_SMEM (3 * PV_STG)               // 62976

// ---------------- stage compute: warp tile 64x32 (R4-proven) ------------------
__device__ __forceinline__ void stage_nt(uint32_t sa, uint32_t sb, int lane,
                                         int wm, int wn, float acc[4][4][4]) {
    const int lr = lane & 15;
    const uint32_t lc16 = (lane >> 4) << 4;
    uint32_t bh[4][2], bl[4][2];
#pragma unroll
    for (int j = 0; j < 2; ++j) {
        uint32_t t4[4];
        const uint32_t roff = (uint32_t)(wn * 32 + j * 16 + lr) * ROWB + lc16;
        ldsm4(t4, sb + roff);
        bh[j*2][0] = t4[0]; bh[j*2+1][0] = t4[1];
        bh[j*2][1] = t4[2]; bh[j*2+1][1] = t4[3];
        ldsm4(t4, sb + PLANE + roff);
        bl[j*2][0] = t4[0]; bl[j*2+1][0] = t4[1];
        bl[j*2][1] = t4[2]; bl[j*2+1][1] = t4[3];
    }
#pragma unroll
    for (int mi = 0; mi < 4; ++mi) {
        uint32_t ah[4], al[4];
        const uint32_t roff = (uint32_t)(wm * 64 + mi * 16 + lr) * ROWB + lc16;
        ldsm4(ah, sa + roff);
        ldsm4(al, sa + PLANE + roff);
#pragma unroll
        for (int nj = 0; nj < 4; ++nj) {
            mma16816(acc[mi][nj], ah, bh[nj]);
            mma16816(acc[mi][nj], ah, bl[nj]);
            mma16816(acc[mi][nj], al, bh[nj]);
        }
    }
}

__device__ __forceinline__ void stage_pv(uint32_t sa, uint32_t sv, int lane,
                                         int wm, int wn, float acc[4][4][4]) {
    const int lr = lane & 15;
    const uint32_t lc16 = (lane >> 4) << 4;
    uint32_t bh[4][2], bl[4][2];
#pragma unroll
    for (int j = 0; j < 2; ++j) {
        uint32_t t4[4];
        const uint32_t off = (uint32_t)lr * VROWB + (uint32_t)(wn * 32 + j * 16) * 2 + lc16;
        ldsm4t(t4, sv + off);
        bh[j*2][0] = t4[0]; bh[j*2][1] = t4[1];
        bh[j*2+1][0] = t4[2]; bh[j*2+1][1] = t4[3];
        ldsm4t(t4, sv + VPLANE + off);
        bl[j*2][0] = t4[0]; bl[j*2][1] = t4[1];
        bl[j*2+1][0] = t4[2]; bl[j*2+1][1] = t4[3];
    }
#pragma unroll
    for (int mi = 0; mi < 4; ++mi) {
        uint32_t ah[4], al[4];
        const uint32_t roff = (uint32_t)(wm * 64 + mi * 16 + lr) * ROWB + lc16;
        ldsm4(ah, sa + roff);
        ldsm4(al, sa + PLANE + roff);
#pragma unroll
        for (int nj = 0; nj < 4; ++nj) {
            mma16816(acc[mi][nj], ah, bh[nj]);
            mma16816(acc[mi][nj], ah, bl[nj]);
            mma16816(acc[mi][nj], al, bh[nj]);
        }
    }
}

#define ACC_INIT float acc[4][4][4];                                    \
    _Pragma("unroll") for (int _i = 0; _i < 4; ++_i)                    \
    _Pragma("unroll") for (int _j = 0; _j < 4; ++_j)                    \
    _Pragma("unroll") for (int _k = 0; _k < 4; ++_k) acc[_i][_j][_k] = 0.f;

// ---------------- cp.async stage issue (256 threads) --------------------------
// NT: thread -> (row = tid>>1, half = tid&1); 4 cpa16 per thread.
__device__ __forceinline__ void issue_nt(uint32_t su, int tid,
                                         const __nv_bfloat16* Ah, const __nv_bfloat16* Al,
                                         const __nv_bfloat16* Bh, const __nv_bfloat16* Bl,
                                         long lda, long ldb, int k0) {
    const int row = tid >> 1, half = tid & 1;
    const uint32_t so = (uint32_t)row * ROWB + (uint32_t)half * 16;
    const long ga = (long)row * lda + k0 + half * 8;
    const long gb = (long)row * ldb + k0 + half * 8;
    cpa16(su + so,                 Ah + ga);
    cpa16(su + PLANE + so,         Al + ga);
    cpa16(su + MAT2 + so,          Bh + gb);
    cpa16(su + MAT2 + PLANE + so,  Bl + gb);
}
// PV: P like NT-A; V: thread -> (vr = tid>>4, vc = tid&15); 2+2 cpa16.
__device__ __forceinline__ void issue_pv(uint32_t su, int tid,
                                         const __nv_bfloat16* Ph, const __nv_bfloat16* Pl,
                                         const __nv_bfloat16* Vh, const __nv_bfloat16* Vl,
                                         int n0, int k0) {
    const int row = tid >> 1, half = tid & 1;
    const uint32_t so = (uint32_t)row * ROWB + (uint32_t)half * 16;
    const long gp = (long)row * SEQ + k0 + half * 8;
    cpa16(su + so,         Ph + gp);
    cpa16(su + PLANE + so, Pl + gp);
    const int vr = tid >> 4, vc = tid & 15;
    const uint32_t vo = su + MAT2 + (uint32_t)vr * VROWB + (uint32_t)vc * 16;
    const long gv = (long)(k0 + vr) * DIM + n0 + vc * 8;
    cpa16(vo,          Vh + gv);
    cpa16(vo + VPLANE, Vl + gv);
}

// ---------------- kernel 0: fp32 -> split planes -----------------------------
__global__ __launch_bounds__(256) void cvt_kernel(const float* __restrict__ src,
                                                  int which, long row0) {
    const long i = ((long)blockIdx.x * 256 + threadIdx.x) * 4;
    __nv_bfloat16* dh = (which == 0) ? g_xh : g_wh;
    __nv_bfloat16* dl = (which == 0) ? g_xl : g_wl;
    dh += row0 * DIM;
    dl += row0 * DIM;
    const float4 v = *(const float4*)(src + i);
    float a[4] = { v.x, v.y, v.z, v.w };
    __nv_bfloat16 h[4], l[4];
#pragma unroll
    for (int j = 0; j < 4; ++j) split_bf16(a[j], h[j], l[j]);
    *(uint2*)(dh + i) = *(uint2*)h;
    *(uint2*)(dl + i) = *(uint2*)l;
}

// ---------------- NT mainloop: 3-stage cp.async, ONE sync per k-step ---------
#define NT_BODY(Ah, Al, Bh, Bl, lda, ldb, NC)                                  \
    extern __shared__ __align__(128) char dsm[];                               \
    const int tid = threadIdx.x;                                               \
    const int lane = tid & 31, wid = tid >> 5;                                 \
    const int wm = wid >> 2, wn = wid & 3;                                     \
    const uint32_t su = smem_u32(dsm);                                         \
    ACC_INIT;                                                                  \
    issue_nt(su,          tid, Ah, Al, Bh, Bl, lda, ldb, 0);  cp_commit();     \
    issue_nt(su + NT_STG, tid, Ah, Al, Bh, Bl, lda, ldb, 16); cp_commit();     \
    for (int c = 0; c < (NC); ++c) {                                           \
        cp_wait<1>();                                                          \
        __syncthreads();                                                       \
        if (c + 2 < (NC))                                                      \
            issue_nt(su + ((c + 2) % 3) * NT_STG, tid, Ah, Al, Bh, Bl,         \
                     lda, ldb, (c + 2) * 16);                                  \
        cp_commit();                                                           \
        const uint32_t sb0 = su + (c % 3) * NT_STG;                            \
        stage_nt(sb0, sb0 + MAT2, lane, wm, wn, acc);                          \
    }

// ---------------- kernel 1: QKV projection (NT) -------------------------------
__global__ __launch_bounds__(256) void gemm_qkv() {
    const int m0 = blockIdx.x * 128;
    const int n0 = blockIdx.y * 128;
    NT_BODY(g_xh + (long)m0 * DIM, g_xl + (long)m0 * DIM,
            g_wh + (long)n0 * DIM, g_wl + (long)n0 * DIM,
            DIM, DIM, DIM / 16);

    const int mat = n0 / DIM;
    const int nl0 = n0 % DIM;
    __nv_bfloat16* dh = (mat == 0) ? g_qh : ((mat == 1) ? g_kh : g_vh);
    __nv_bfloat16* dl = (mat == 0) ? g_ql : ((mat == 1) ? g_kl : g_vl);
    const int r = lane >> 2, cc = (lane & 3) * 2;
#pragma unroll
    for (int mi = 0; mi < 4; ++mi)
#pragma unroll
        for (int nj = 0; nj < 4; ++nj)
#pragma unroll
            for (int h2 = 0; h2 < 2; ++h2) {
                const int m = m0 + wm * 64 + mi * 16 + r + h2 * 8;
                const int n = nl0 + wn * 32 + nj * 8 + cc;
                __nv_bfloat162 hv, lv;
                split_bf16(acc[mi][nj][h2 * 2 + 0], hv.x, lv.x);
                split_bf16(acc[mi][nj][h2 * 2 + 1], hv.y, lv.y);
                *(__nv_bfloat162*)(dh + (long)m * DIM + n) = hv;
                *(__nv_bfloat162*)(dl + (long)m * DIM + n) = lv;
            }
}

// ---------------- kernel 2: causal scores (NT) --------------------------------
__global__ __launch_bounds__(256) void gemm_scores() {
    const int mi_t = gridDim.x - 1 - blockIdx.x;    // longest first
    if ((int)blockIdx.y > mi_t) return;             // fully above diagonal
    const int m0 = mi_t * 128, n0 = blockIdx.y * 128, b = blockIdx.z;
    NT_BODY(g_qh + ((long)b * SEQ + m0) * DIM, g_ql + ((long)b * SEQ + m0) * DIM,
            g_kh + ((long)b * SEQ + n0) * DIM, g_kl + ((long)b * SEQ + n0) * DIM,
            DIM, DIM, DIM / 16);

    const float scale = 0.036084391824351615f;      // 1/sqrt(768)
    float* Sg = g_S + (size_t)b * SEQ * SEQ;
    const int r = lane >> 2, cc = (lane & 3) * 2;
#pragma unroll
    for (int mi = 0; mi < 4; ++mi)
#pragma unroll
        for (int nj = 0; nj < 4; ++nj)
#pragma unroll
            for (int h2 = 0; h2 < 2; ++h2) {
                const int m = m0 + wm * 64 + mi * 16 + r + h2 * 8;
                const int n = n0 + wn * 32 + nj * 8 + cc;
                float2 v = make_float2(acc[mi][nj][h2 * 2 + 0] * scale,
                                       acc[mi][nj][h2 * 2 + 1] * scale);
                *(float2*)(Sg + (size_t)m * SEQ + n) = v;
            }
}

// ---------------- kernel 3: softmax + split-bf16 P -----------------------------
__global__ __launch_bounds__(256) void softmax_kernel() {
    const int rid = blockIdx.x;
    const int q = rid & (SEQ - 1);
    float* __restrict__ row = g_S + (size_t)rid * SEQ;
    __nv_bfloat16* __restrict__ ph = g_ph + (size_t)rid * SEQ;
    __nv_bfloat16* __restrict__ pl = g_pl + (size_t)rid * SEQ;
    const int L = q + 1;
    const int tid = threadIdx.x;
    __shared__ float red[256];

    float m = -1e30f;
    for (int k = tid; k < L; k += 256) m = fmaxf(m, row[k]);
    red[tid] = m;
    __syncthreads();
#pragma unroll
    for (int s = 128; s > 0; s >>= 1) {
        if (tid < s) red[tid] = fmaxf(red[tid], red[tid + s]);
        __syncthreads();
    }
    m = red[0];
    __syncthreads();

    float ssum = 0.f;
    for (int k = tid; k < L; k += 256) {
        float e = __expf(row[k] - m);
        row[k] = e;
        ssum += e;
    }
    red[tid] = ssum;
    __syncthreads();
#pragma unroll
    for (int s = 128; s > 0; s >>= 1) {
        if (tid < s) red[tid] += red[tid + s];
        __syncthreads();
    }
    const float inv = 1.0f / red[0];

    for (int k = tid; k < L; k += 256) {
        __nv_bfloat16 h, l;
        split_bf16(row[k] * inv, h, l);
        ph[k] = h;
        pl[k] = l;
    }
    const int kend = (q & ~127) + 128;
    const __nv_bfloat16 z = __float2bfloat16(0.f);
    for (int k = L + tid; k < kend; k += 256) { ph[k] = z; pl[k] = z; }
}

// ---------------- kernel 4: O = P V --------------------------------------------
__global__ __launch_bounds__(256) void gemm_pv(float* __restrict__ out) {
    const int mi_t = gridDim.x - 1 - blockIdx.x;    // longest K first
    const int m0 = mi_t * 128, n0 = blockIdx.y * 128, b = blockIdx.z;
    const __nv_bfloat16* Ph = g_ph + ((size_t)b * SEQ + m0) * SEQ;
    const __nv_bfloat16* Pl = g_pl + ((size_t)b * SEQ + m0) * SEQ;
    const __nv_bfloat16* Vh = g_vh + (long)b * SEQ * DIM;
    const __nv_bfloat16* Vl = g_vl + (long)b * SEQ * DIM;

    extern __shared__ __align__(128) char dsm[];
    const int tid = threadIdx.x;
    const int lane = tid & 31, wid = tid >> 5;
    const int wm = wid >> 2, wn = wid & 3;
    const uint32_t su = smem_u32(dsm);
    ACC_INIT;
    const int NC = (m0 + 128) / 16;

    issue_pv(su,          tid, Ph, Pl, Vh, Vl, n0, 0);  cp_commit();
    issue_pv(su + PV_STG, tid, Ph, Pl, Vh, Vl, n0, 16); cp_commit();
    for (int c = 0; c < NC; ++c) {
        cp_wait<1>();
        __syncthreads();
        if (c + 2 < NC)
            issue_pv(su + ((c + 2) % 3) * PV_STG, tid, Ph, Pl, Vh, Vl, n0,
                     (c + 2) * 16);
        cp_commit();
        const uint32_t sb0 = su + (c % 3) * PV_STG;
        stage_pv(sb0, sb0 + MAT2, lane, wm, wn, acc);
    }

    float* Og = out + (long)b * SEQ * DIM;
    const int r = lane >> 2, cc = (lane & 3) * 2;
#pragma unroll
    for (int mi = 0; mi < 4; ++mi)
#pragma unroll
        for (int nj = 0; nj < 4; ++nj)
#pragma unroll
            for (int h2 = 0; h2 < 2; ++h2) {
                const int m = m0 + wm * 64 + mi * 16 + r + h2 * 8;
                const int n = n0 + wn * 32 + nj * 8 + cc;
                float2 v = make_float2(acc[mi][nj][h2 * 2 + 0],
                                       acc[mi][nj][h2 * 2 + 1]);
                *(float2*)(Og + (long)m * DIM + n) = v;
            }
}

// ---------------- launch ---------------------------------------------------------
extern "C" void kernel_launch(void* const* d_in, const int* in_sizes, int n_in,
                              void* d_out, int out_size) {
    const float* x  = (const float*)d_in[0];
    const float* Wq = (const float*)d_in[1];
    const float* Wk = (const float*)d_in[2];
    const float* Wv = (const float*)d_in[3];
    float* out = (float*)d_out;

    cudaFuncSetAttribute(gemm_qkv,    cudaFuncAttributeMaxDynamicSharedMemorySize, NT_SMEM);
    cudaFuncSetAttribute(gemm_scores, cudaFuncAttributeMaxDynamicSharedMemorySize, NT_SMEM);
    cudaFuncSetAttribute(gemm_pv,     cudaFuncAttributeMaxDynamicSharedMemorySize, PV_SMEM);

    cvt_kernel<<<(long)MROWS * DIM / 4 / 256, 256>>>(x,  0, 0);
    cvt_kernel<<<(long)DIM * DIM / 4 / 256, 256>>>(Wq, 1, 0);
    cvt_kernel<<<(long)DIM * DIM / 4 / 256, 256>>>(Wk, 1, DIM);
    cvt_kernel<<<(long)DIM * DIM / 4 / 256, 256>>>(Wv, 1, 2 * DIM);

    gemm_qkv<<<dim3(MROWS / 128, NQKV / 128), 256, NT_SMEM>>>();
    gemm_scores<<<dim3(SEQ / 128, SEQ / 128, BATCH), 256, NT_SMEM>>>();
    softmax_kernel<<<BATCH * SEQ, 256>>>();
    gemm_pv<<<dim3(SEQ / 128, DIM / 128, BATCH), 256, PV_SMEM>>>(out);
}

// round 7
// speedup vs baseline: 1.3816x; 1.1818x over previous
#include <cuda_runtime.h>
#include <cuda_bf16.h>
#include <stdint.h>

#define BATCH 4
#define SEQ   2048
#define DIM   768
#define MROWS 8192            // B*S
#define NQKV  2304            // 3*DIM

// ---------------- device scratch: split-bf16 planes -------------------------
__device__ __align__(128) __nv_bfloat16 g_xh[(long)MROWS * DIM];
__device__ __align__(128) __nv_bfloat16 g_xl[(long)MROWS * DIM];
__device__ __align__(128) __nv_bfloat16 g_wh[(long)NQKV * DIM];
__device__ __align__(128) __nv_bfloat16 g_wl[(long)NQKV * DIM];
__device__ __align__(128) __nv_bfloat16 g_qh[(long)MROWS * DIM];
__device__ __align__(128) __nv_bfloat16 g_ql[(long)MROWS * DIM];
__device__ __align__(128) __nv_bfloat16 g_kh[(long)MROWS * DIM];
__device__ __align__(128) __nv_bfloat16 g_kl[(long)MROWS * DIM];
__device__ __align__(128) __nv_bfloat16 g_vh[(long)MROWS * DIM];   // [b*S+s][d]
__device__ __align__(128) __nv_bfloat16 g_vl[(long)MROWS * DIM];
__device__ __align__(128) __nv_bfloat16 g_ph[(size_t)BATCH * SEQ * SEQ];
__device__ __align__(128) __nv_bfloat16 g_pl[(size_t)BATCH * SEQ * SEQ];
__device__ float g_S[(size_t)BATCH * SEQ * SEQ];

// ---------------- PTX helpers (portable, no arch-'a' features) --------------
__device__ __forceinline__ uint32_t smem_u32(const void* p) {
    uint32_t a;
    asm("{ .reg .u64 t; cvta.to.shared.u64 t, %1; cvt.u32.u64 %0, t; }"
        : "=r"(a) : "l"(p));
    return a;
}
__device__ __forceinline__ void ldsm4(uint32_t r[4], uint32_t addr) {
    asm volatile("ldmatrix.sync.aligned.m8n8.x4.shared.b16 {%0,%1,%2,%3}, [%4];"
                 : "=r"(r[0]), "=r"(r[1]), "=r"(r[2]), "=r"(r[3]) : "r"(addr));
}
__device__ __forceinline__ void ldsm4t(uint32_t r[4], uint32_t addr) {
    asm volatile("ldmatrix.sync.aligned.m8n8.x4.trans.shared.b16 {%0,%1,%2,%3}, [%4];"
                 : "=r"(r[0]), "=r"(r[1]), "=r"(r[2]), "=r"(r[3]) : "r"(addr));
}
__device__ __forceinline__ void mma16816(float d[4], const uint32_t a[4],
                                         const uint32_t b[2]) {
    asm volatile(
        "mma.sync.aligned.m16n8k16.row.col.f32.bf16.bf16.f32 "
        "{%0,%1,%2,%3}, {%4,%5,%6,%7}, {%8,%9}, {%0,%1,%2,%3};"
        : "+f"(d[0]), "+f"(d[1]), "+f"(d[2]), "+f"(d[3])
        : "r"(a[0]), "r"(a[1]), "r"(a[2]), "r"(a[3]), "r"(b[0]), "r"(b[1]));
}
__device__ __forceinline__ void split_bf16(float v, __nv_bfloat16& h, __nv_bfloat16& l) {
    h = __float2bfloat16(v);
    l = __float2bfloat16(v - __bfloat162float(h));
}

// ---------------- smem geometry: k32 stages, double buffered -----------------
// A/B/P tiles: 128 rows x 32 k, pitch 40 bf16 (80B). Row offsets mod 128B are
// all distinct within 8-row groups -> conflict-free ldmatrix.
#define ROW2B   80
#define PLANE2  10240                      // 128*80
#define MAT2B   (2 * PLANE2)               // hi+lo planes = 20480
#define NT_STG  (2 * MAT2B)                // A+B = 40960
#define NT_SMEM (2 * NT_STG)               // 81920

// V tile: 32 rows x 128 cols, pitch 136 bf16 (272B)
#define VROWB   272
#define VPLANE2 (32 * VROWB)               // 8704
#define PV_STG  (MAT2B + 2 * VPLANE2)      // 20480 + 17408 = 37888
#define PV_SMEM (2 * PV_STG)               // 75776

// ---------------- stage compute: warp tile 64x32, one k16 sub-block ----------
// sub in {0,1} selects the 16-k half of the 32-k stage.
__device__ __forceinline__ void stage_nt(uint32_t sa, uint32_t sb, int sub, int lane,
                                         int wm, int wn, float acc[4][4][4]) {
    const int lr = lane & 15;
    const uint32_t lc16 = ((lane >> 4) << 4) + (uint32_t)sub * 32;
    uint32_t bh[4][2], bl[4][2];
#pragma unroll
    for (int j = 0; j < 2; ++j) {
        uint32_t t4[4];
        const uint32_t roff = (uint32_t)(wn * 32 + j * 16 + lr) * ROW2B + lc16;
        ldsm4(t4, sb + roff);
        bh[j*2][0] = t4[0]; bh[j*2+1][0] = t4[1];
        bh[j*2][1] = t4[2]; bh[j*2+1][1] = t4[3];
        ldsm4(t4, sb + PLANE2 + roff);
        bl[j*2][0] = t4[0]; bl[j*2+1][0] = t4[1];
        bl[j*2][1] = t4[2]; bl[j*2+1][1] = t4[3];
    }
#pragma unroll
    for (int mi = 0; mi < 4; ++mi) {
        uint32_t ah[4], al[4];
        const uint32_t roff = (uint32_t)(wm * 64 + mi * 16 + lr) * ROW2B + lc16;
        ldsm4(ah, sa + roff);
        ldsm4(al, sa + PLANE2 + roff);
#pragma unroll
        for (int nj = 0; nj < 4; ++nj) {
            mma16816(acc[mi][nj], ah, bh[nj]);
            mma16816(acc[mi][nj], ah, bl[nj]);
            mma16816(acc[mi][nj], al, bh[nj]);
        }
    }
}

__device__ __forceinline__ void stage_pv(uint32_t sa, uint32_t sv, int sub, int lane,
                                         int wm, int wn, float acc[4][4][4]) {
    const int lr = lane & 15;
    const uint32_t lc16 = (lane >> 4) << 4;
    const uint32_t pc16 = lc16 + (uint32_t)sub * 32;
    uint32_t bh[4][2], bl[4][2];
#pragma unroll
    for (int j = 0; j < 2; ++j) {
        uint32_t t4[4];
        const uint32_t off = (uint32_t)(sub * 16 + lr) * VROWB +
                             (uint32_t)(wn * 32 + j * 16) * 2 + lc16;
        ldsm4t(t4, sv + off);
        bh[j*2][0] = t4[0]; bh[j*2][1] = t4[1];
        bh[j*2+1][0] = t4[2]; bh[j*2+1][1] = t4[3];
        ldsm4t(t4, sv + VPLANE2 + off);
        bl[j*2][0] = t4[0]; bl[j*2][1] = t4[1];
        bl[j*2+1][0] = t4[2]; bl[j*2+1][1] = t4[3];
    }
#pragma unroll
    for (int mi = 0; mi < 4; ++mi) {
        uint32_t ah[4], al[4];
        const uint32_t roff = (uint32_t)(wm * 64 + mi * 16 + lr) * ROW2B + pc16;
        ldsm4(ah, sa + roff);
        ldsm4(al, sa + PLANE2 + roff);
#pragma unroll
        for (int nj = 0; nj < 4; ++nj) {
            mma16816(acc[mi][nj], ah, bh[nj]);
            mma16816(acc[mi][nj], ah, bl[nj]);
            mma16816(acc[mi][nj], al, bh[nj]);
        }
    }
}

#define ACC_INIT float acc[4][4][4];                                    \
    _Pragma("unroll") for (int _i = 0; _i < 4; ++_i)                    \
    _Pragma("unroll") for (int _j = 0; _j < 4; ++_j)                    \
    _Pragma("unroll") for (int _k = 0; _k < 4; ++_k) acc[_i][_j][_k] = 0.f;

// ---------------- k16 half-stage loaders (register prefetch, R4 pattern) -----
struct Frag4 { uint4 v[4]; };

__device__ __forceinline__ Frag4 ld16_nt(const __nv_bfloat16* Ah, const __nv_bfloat16* Al,
                                         const __nv_bfloat16* Bh, const __nv_bfloat16* Bl,
                                         long lda, long ldb, int k0, int tid) {
    const int row = tid >> 1, half = tid & 1;
    const long ga = (long)row * lda + k0 + half * 8;
    const long gb = (long)row * ldb + k0 + half * 8;
    Frag4 f;
    f.v[0] = *(const uint4*)(Ah + ga);
    f.v[1] = *(const uint4*)(Al + ga);
    f.v[2] = *(const uint4*)(Bh + gb);
    f.v[3] = *(const uint4*)(Bl + gb);
    return f;
}
__device__ __forceinline__ void st16_nt(char* dsm, int stg, int sub, Frag4 f, int tid) {
    const int row = tid >> 1, half = tid & 1;
    char* base = dsm + stg * NT_STG;
    const uint32_t so = (uint32_t)row * ROW2B + (uint32_t)sub * 32 + (uint32_t)half * 16;
    *(uint4*)(base + so)                  = f.v[0];
    *(uint4*)(base + PLANE2 + so)         = f.v[1];
    *(uint4*)(base + MAT2B + so)          = f.v[2];
    *(uint4*)(base + MAT2B + PLANE2 + so) = f.v[3];
}

__device__ __forceinline__ Frag4 ld16_pv(const __nv_bfloat16* Ph, const __nv_bfloat16* Pl,
                                         const __nv_bfloat16* Vh, const __nv_bfloat16* Vl,
                                         int n0, int k0, int tid) {
    const int row = tid >> 1, half = tid & 1;
    const long gp = (long)row * SEQ + k0 + half * 8;
    const int vr = tid >> 4, vc = (tid & 15) * 8;
    const long gv = (long)(k0 + vr) * DIM + n0 + vc;
    Frag4 f;
    f.v[0] = *(const uint4*)(Ph + gp);
    f.v[1] = *(const uint4*)(Pl + gp);
    f.v[2] = *(const uint4*)(Vh + gv);
    f.v[3] = *(const uint4*)(Vl + gv);
    return f;
}
__device__ __forceinline__ void st16_pv(char* dsm, int stg, int sub, Frag4 f, int tid) {
    const int row = tid >> 1, half = tid & 1;
    char* base = dsm + stg * PV_STG;
    const uint32_t so = (uint32_t)row * ROW2B + (uint32_t)sub * 32 + (uint32_t)half * 16;
    *(uint4*)(base + so)          = f.v[0];
    *(uint4*)(base + PLANE2 + so) = f.v[1];
    const int vr = tid >> 4, vc = (tid & 15) * 8;
    const uint32_t vo = (uint32_t)(sub * 16 + vr) * VROWB + (uint32_t)vc * 2;
    *(uint4*)(base + MAT2B + vo)           = f.v[2];
    *(uint4*)(base + MAT2B + VPLANE2 + vo) = f.v[3];
}

// ---------------- kernel 0: fp32 -> split planes -----------------------------
__global__ __launch_bounds__(256) void cvt_kernel(const float* __restrict__ src,
                                                  int which, long row0) {
    const long i = ((long)blockIdx.x * 256 + threadIdx.x) * 4;
    __nv_bfloat16* dh = (which == 0) ? g_xh : g_wh;
    __nv_bfloat16* dl = (which == 0) ? g_xl : g_wl;
    dh += row0 * DIM;
    dl += row0 * DIM;
    const float4 v = *(const float4*)(src + i);
    float a[4] = { v.x, v.y, v.z, v.w };
    __nv_bfloat16 h[4], l[4];
#pragma unroll
    for (int j = 0; j < 4; ++j) split_bf16(a[j], h[j], l[j]);
    *(uint2*)(dh + i) = *(uint2*)h;
    *(uint2*)(dl + i) = *(uint2*)l;
}

// ---------------- NT mainloop: k32 double buffer, ONE sync per 32-k ----------
#define NT_BODY(Ah, Al, Bh, Bl, lda, ldb, NC2)                                 \
    extern __shared__ __align__(128) char dsm[];                               \
    const int tid = threadIdx.x;                                               \
    const int lane = tid & 31, wid = tid >> 5;                                 \
    const int wm = wid >> 2, wn = wid & 3;                                     \
    const uint32_t su = smem_u32(dsm);                                         \
    ACC_INIT;                                                                  \
    {                                                                          \
        Frag4 f0 = ld16_nt(Ah, Al, Bh, Bl, lda, ldb, 0, tid);                  \
        Frag4 f1 = ld16_nt(Ah, Al, Bh, Bl, lda, ldb, 16, tid);                 \
        st16_nt(dsm, 0, 0, f0, tid);                                           \
        st16_nt(dsm, 0, 1, f1, tid);                                           \
    }                                                                          \
    __syncthreads();                                                           \
    for (int c = 0; c < (NC2); ++c) {                                          \
        const int buf = c & 1;                                                 \
        const uint32_t sb0 = su + buf * NT_STG;                                \
        const bool more = (c + 1 < (NC2));                                     \
        Frag4 f;                                                               \
        if (more) f = ld16_nt(Ah, Al, Bh, Bl, lda, ldb, (c + 1) * 32, tid);    \
        stage_nt(sb0, sb0 + MAT2B, 0, lane, wm, wn, acc);                      \
        if (more) {                                                            \
            st16_nt(dsm, buf ^ 1, 0, f, tid);                                  \
            f = ld16_nt(Ah, Al, Bh, Bl, lda, ldb, (c + 1) * 32 + 16, tid);     \
        }                                                                      \
        stage_nt(sb0, sb0 + MAT2B, 1, lane, wm, wn, acc);                      \
        if (more) {                                                            \
            st16_nt(dsm, buf ^ 1, 1, f, tid);                                  \
            __syncthreads();                                                   \
        }                                                                      \
    }

// ---------------- kernel 1: QKV projection (NT) -------------------------------
__global__ __launch_bounds__(256, 2) void gemm_qkv() {
    const int m0 = blockIdx.x * 128;
    const int n0 = blockIdx.y * 128;
    NT_BODY(g_xh + (long)m0 * DIM, g_xl + (long)m0 * DIM,
            g_wh + (long)n0 * DIM, g_wl + (long)n0 * DIM,
            DIM, DIM, DIM / 32);

    const int mat = n0 / DIM;
    const int nl0 = n0 % DIM;
    __nv_bfloat16* dh = (mat == 0) ? g_qh : ((mat == 1) ? g_kh : g_vh);
    __nv_bfloat16* dl = (mat == 0) ? g_ql : ((mat == 1) ? g_kl : g_vl);
    const int r = lane >> 2, cc = (lane & 3) * 2;
#pragma unroll
    for (int mi = 0; mi < 4; ++mi)
#pragma unroll
        for (int nj = 0; nj < 4; ++nj)
#pragma unroll
            for (int h2 = 0; h2 < 2; ++h2) {
                const int m = m0 + wm * 64 + mi * 16 + r + h2 * 8;
                const int n = nl0 + wn * 32 + nj * 8 + cc;
                __nv_bfloat162 hv, lv;
                split_bf16(acc[mi][nj][h2 * 2 + 0], hv.x, lv.x);
                split_bf16(acc[mi][nj][h2 * 2 + 1], hv.y, lv.y);
                *(__nv_bfloat162*)(dh + (long)m * DIM + n) = hv;
                *(__nv_bfloat162*)(dl + (long)m * DIM + n) = lv;
            }
}

// ---------------- kernel 2: causal scores (NT) --------------------------------
__global__ __launch_bounds__(256, 2) void gemm_scores() {
    const int mi_t = gridDim.x - 1 - blockIdx.x;    // longest first
    if ((int)blockIdx.y > mi_t) return;             // fully above diagonal
    const int m0 = mi_t * 128, n0 = blockIdx.y * 128, b = blockIdx.z;
    NT_BODY(g_qh + ((long)b * SEQ + m0) * DIM, g_ql + ((long)b * SEQ + m0) * DIM,
            g_kh + ((long)b * SEQ + n0) * DIM, g_kl + ((long)b * SEQ + n0) * DIM,
            DIM, DIM, DIM / 32);

    const float scale = 0.036084391824351615f;      // 1/sqrt(768)
    float* Sg = g_S + (size_t)b * SEQ * SEQ;
    const int r = lane >> 2, cc = (lane & 3) * 2;
#pragma unroll
    for (int mi = 0; mi < 4; ++mi)
#pragma unroll
        for (int nj = 0; nj < 4; ++nj)
#pragma unroll
            for (int h2 = 0; h2 < 2; ++h2) {
                const int m = m0 + wm * 64 + mi * 16 + r + h2 * 8;
                const int n = n0 + wn * 32 + nj * 8 + cc;
                float2 v = make_float2(acc[mi][nj][h2 * 2 + 0] * scale,
                                       acc[mi][nj][h2 * 2 + 1] * scale);
                *(float2*)(Sg + (size_t)m * SEQ + n) = v;
            }
}

// ---------------- kernel 3: softmax + split-bf16 P -----------------------------
__global__ __launch_bounds__(256) void softmax_kernel() {
    const int rid = blockIdx.x;
    const int q = rid & (SEQ - 1);
    float* __restrict__ row = g_S + (size_t)rid * SEQ;
    __nv_bfloat16* __restrict__ ph = g_ph + (size_t)rid * SEQ;
    __nv_bfloat16* __restrict__ pl = g_pl + (size_t)rid * SEQ;
    const int L = q + 1;
    const int tid = threadIdx.x;
    __shared__ float red[256];

    float m = -1e30f;
    for (int k = tid; k < L; k += 256) m = fmaxf(m, row[k]);
    red[tid] = m;
    __syncthreads();
#pragma unroll
    for (int s = 128; s > 0; s >>= 1) {
        if (tid < s) red[tid] = fmaxf(red[tid], red[tid + s]);
        __syncthreads();
    }
    m = red[0];
    __syncthreads();

    float ssum = 0.f;
    for (int k = tid; k < L; k += 256) {
        float e = __expf(row[k] - m);
        row[k] = e;
        ssum += e;
    }
    red[tid] = ssum;
    __syncthreads();
#pragma unroll
    for (int s = 128; s > 0; s >>= 1) {
        if (tid < s) red[tid] += red[tid + s];
        __syncthreads();
    }
    const float inv = 1.0f / red[0];

    for (int k = tid; k < L; k += 256) {
        __nv_bfloat16 h, l;
        split_bf16(row[k] * inv, h, l);
        ph[k] = h;
        pl[k] = l;
    }
    const int kend = (q & ~127) + 128;
    const __nv_bfloat16 z = __float2bfloat16(0.f);
    for (int k = L + tid; k < kend; k += 256) { ph[k] = z; pl[k] = z; }
}

// ---------------- kernel 4: O = P V --------------------------------------------
__global__ __launch_bounds__(256, 2) void gemm_pv(float* __restrict__ out) {
    const int mi_t = gridDim.x - 1 - blockIdx.x;    // longest K first
    const int m0 = mi_t * 128, n0 = blockIdx.y * 128, b = blockIdx.z;
    const __nv_bfloat16* Ph = g_ph + ((size_t)b * SEQ + m0) * SEQ;
    const __nv_bfloat16* Pl = g_pl + ((size_t)b * SEQ + m0) * SEQ;
    const __nv_bfloat16* Vh = g_vh + (long)b * SEQ * DIM;
    const __nv_bfloat16* Vl = g_vl + (long)b * SEQ * DIM;

    extern __shared__ __align__(128) char dsm[];
    const int tid = threadIdx.x;
    const int lane = tid & 31, wid = tid >> 5;
    const int wm = wid >> 2, wn = wid & 3;
    const uint32_t su = smem_u32(dsm);
    ACC_INIT;
    const int NC2 = (m0 + 128) / 32;

    {
        Frag4 f0 = ld16_pv(Ph, Pl, Vh, Vl, n0, 0, tid);
        Frag4 f1 = ld16_pv(Ph, Pl, Vh, Vl, n0, 16, tid);
        st16_pv(dsm, 0, 0, f0, tid);
        st16_pv(dsm, 0, 1, f1, tid);
    }
    __syncthreads();
    for (int c = 0; c < NC2; ++c) {
        const int buf = c & 1;
        const uint32_t sb0 = su + buf * PV_STG;
        const bool more = (c + 1 < NC2);
        Frag4 f;
        if (more) f = ld16_pv(Ph, Pl, Vh, Vl, n0, (c + 1) * 32, tid);
        stage_pv(sb0, sb0 + MAT2B, 0, lane, wm, wn, acc);
        if (more) {
            st16_pv(dsm, buf ^ 1, 0, f, tid);
            f = ld16_pv(Ph, Pl, Vh, Vl, n0, (c + 1) * 32 + 16, tid);
        }
        stage_pv(sb0, sb0 + MAT2B, 1, lane, wm, wn, acc);
        if (more) {
            st16_pv(dsm, buf ^ 1, 1, f, tid);
            __syncthreads();
        }
    }

    float* Og = out + (long)b * SEQ * DIM;
    const int r = lane >> 2, cc = (lane & 3) * 2;
#pragma unroll
    for (int mi = 0; mi < 4; ++mi)
#pragma unroll
        for (int nj = 0; nj < 4; ++nj)
#pragma unroll
            for (int h2 = 0; h2 < 2; ++h2) {
                const int m = m0 + wm * 64 + mi * 16 + r + h2 * 8;
                const int n = n0 + wn * 32 + nj * 8 + cc;
                float2 v = make_float2(acc[mi][nj][h2 * 2 + 0],
                                       acc[mi][nj][h2 * 2 + 1]);
                *(float2*)(Og + (long)m * DIM + n) = v;
            }
}

// ---------------- launch ---------------------------------------------------------
extern "C" void kernel_launch(void* const* d_in, const int* in_sizes, int n_in,
                              void* d_out, int out_size) {
    const float* x  = (const float*)d_in[0];
    const float* Wq = (const float*)d_in[1];
    const float* Wk = (const float*)d_in[2];
    const float* Wv = (const float*)d_in[3];
    float* out = (float*)d_out;

    cudaFuncSetAttribute(gemm_qkv,    cudaFuncAttributeMaxDynamicSharedMemorySize, NT_SMEM);
    cudaFuncSetAttribute(gemm_scores, cudaFuncAttributeMaxDynamicSharedMemorySize, NT_SMEM);
    cudaFuncSetAttribute(gemm_pv,     cudaFuncAttributeMaxDynamicSharedMemorySize, PV_SMEM);

    cvt_kernel<<<(long)MROWS * DIM / 4 / 256, 256>>>(x,  0, 0);
    cvt_kernel<<<(long)DIM * DIM / 4 / 256, 256>>>(Wq, 1, 0);
    cvt_kernel<<<(long)DIM * DIM / 4 / 256, 256>>>(Wk, 1, DIM);
    cvt_kernel<<<(long)DIM * DIM / 4 / 256, 256>>>(Wv, 1, 2 * DIM);

    gemm_qkv<<<dim3(MROWS / 128, NQKV / 128), 256, NT_SMEM>>>();
    gemm_scores<<<dim3(SEQ / 128, SEQ / 128, BATCH), 256, NT_SMEM>>>();
    softmax_kernel<<<BATCH * SEQ, 256>>>();
    gemm_pv<<<dim3(SEQ / 128, DIM / 128, BATCH), 256, PV_SMEM>>>(out);
}